// round 1
// baseline (speedup 1.0000x reference)
#include <cuda_runtime.h>

#define BB 128
#define TQ 64
#define TK 200
#define TKP 224
#define DD 64
#define HH 10
#define NTHREADS 512

// Shared memory layout (float offsets)
#define OFF_SEQRM 0          // [200][64]            12800
#define OFF_SEQT  12800      // [64][225] (also sP)  14400
#define OFF_A     27200      // atT [64][64]          4096
#define OFF_TGT   31296      // [64][65]              4160
#define OFF_DECAY 35456      // [224]
#define OFF_VALID 35680      // [224]
#define OFF_AW    35904      // [10][64]
#define OFF_ABIAS 36544      // [16]
#define OFF_AOUT  36560      // [16]
#define OFF_FR    36576      // [64]
#define OFF_FI    36640      // [64]
#define SMEM_FLOATS 36704    // 146816 bytes

__device__ __forceinline__ float fast_tanh(float x) {
    x = fminf(fmaxf(x, -15.f), 15.f);
    float e2 = __expf(2.f * x);
    return __fdividef(e2 - 1.f, e2 + 1.f);
}

__global__ __launch_bounds__(NTHREADS, 1)
void fta_kernel(const float* __restrict__ seq,
                const float* __restrict__ dtn,
                const float* __restrict__ target,
                const int*   __restrict__ vmask,
                const float* __restrict__ fr,
                const float* __restrict__ fi,
                const float* __restrict__ Aw,
                const float* __restrict__ Ab,
                const float* __restrict__ Aout,
                float* __restrict__ out)
{
    extern __shared__ float sm[];
    float* sSeqRM = sm + OFF_SEQRM;
    float* sSeqT  = sm + OFF_SEQT;
    float* sP     = sm + OFF_SEQT;   // alias: seqT dead after score GEMM
    float* sA     = sm + OFF_A;
    float* sTgt   = sm + OFF_TGT;
    float* sDecay = sm + OFF_DECAY;
    float* sValid = sm + OFF_VALID;
    float* sAw    = sm + OFF_AW;
    float* sAb    = sm + OFF_ABIAS;
    float* sAout  = sm + OFF_AOUT;
    float* sFr    = sm + OFF_FR;
    float* sFi    = sm + OFF_FI;

    const int b    = blockIdx.x;
    const int tid  = threadIdx.x;
    const int lane = tid & 31;
    const int warp = tid >> 5;     // 0..15, warp owns t rows [warp*4, warp*4+4)

    // ---------- Phase A: cooperative loads ----------
    {
        const float4* g4 = (const float4*)(seq + (size_t)b * TK * DD);
        float4* s4 = (float4*)sSeqRM;
        #pragma unroll
        for (int i = tid; i < TK * DD / 4; i += NTHREADS) s4[i] = g4[i];

        const float* gT = target + (size_t)b * TQ * DD;
        for (int i = tid; i < TQ * DD; i += NTHREADS) {
            int t = i >> 6, d = i & 63;
            sTgt[t * 65 + d] = gT[i];
        }
        if (tid < HH * DD) sAw[tid] = Aw[tid];
        if (tid < DD) { sFr[tid] = fr[tid]; sFi[tid] = fi[tid]; }
        if (tid < HH) { sAb[tid] = Ab[tid]; sAout[tid] = Aout[tid]; }
    }
    __syncthreads();

    // ---------- Phase B: transpose seq + zero pad, Fourier decay ----------
    for (int i = tid; i < TK * DD; i += NTHREADS) {
        int k = i >> 6, d = i & 63;
        sSeqT[d * 225 + k] = sSeqRM[i];
    }
    for (int i = tid; i < DD * (225 - TK); i += NTHREADS) {
        int d = i / (225 - TK), kk = TK + i % (225 - TK);
        sSeqT[d * 225 + kk] = 0.f;
    }
    if (tid < TKP) {
        float dec = 0.f, val = 0.f;
        if (tid < TK) {
            const int   m  = vmask[b * TK + tid];
            const float dt = dtn[b * TK + tid];
            // w_j = 2*pi*(j/63/2)*dt = (pi/63)*j*dt ; both halves identical
            const float th = (3.14159265358979323846f / 63.f) * dt;
            float acc = 0.f;
            #pragma unroll 8
            for (int j = 0; j < DD; j++) {
                float s, c;
                __sincosf(th * (float)j, &s, &c);
                acc = fmaf(c, sFr[j], acc);
                acc = fmaf(-s, sFi[j], acc);
            }
            float dcy = fminf(fmaxf(acc * (1.f / 128.f), 0.f), 1.f);
            if (m != 0) { dec = dcy; val = 1.f; }
        }
        sDecay[tid] = dec;
        sValid[tid] = val;
    }
    __syncthreads();

    // ---------- Phase C: MLP scores (10 rank-64 GEMMs, scores in registers) ----------
    float sc[4][7];
    #pragma unroll
    for (int i = 0; i < 4; i++)
        #pragma unroll
        for (int j = 0; j < 7; j++) sc[i][j] = 0.f;

    const int t0 = warp * 4;
    for (int h = 0; h < HH; h++) {
        // build atT[d][t] = A_w[h][d] * target[t][d]
        for (int i = tid; i < DD * TQ; i += NTHREADS) {
            int d = i >> 6, t = i & 63;
            sA[i] = sAw[h * 64 + d] * sTgt[t * 65 + d];
        }
        __syncthreads();

        float acc[4][7];
        #pragma unroll
        for (int i = 0; i < 4; i++)
            #pragma unroll
            for (int j = 0; j < 7; j++) acc[i][j] = 0.f;

        #pragma unroll 16
        for (int d = 0; d < DD; d++) {
            const float4 a4 = *(const float4*)(sA + d * 64 + t0);  // broadcast per warp
            float bv[7];
            #pragma unroll
            for (int j = 0; j < 7; j++) bv[j] = sSeqT[d * 225 + lane + 32 * j];
            #pragma unroll
            for (int j = 0; j < 7; j++) {
                acc[0][j] = fmaf(a4.x, bv[j], acc[0][j]);
                acc[1][j] = fmaf(a4.y, bv[j], acc[1][j]);
                acc[2][j] = fmaf(a4.z, bv[j], acc[2][j]);
                acc[3][j] = fmaf(a4.w, bv[j], acc[3][j]);
            }
        }
        const float ao = sAout[h], ab = sAb[h];
        #pragma unroll
        for (int i = 0; i < 4; i++)
            #pragma unroll
            for (int j = 0; j < 7; j++)
                sc[i][j] = fmaf(ao, fast_tanh(acc[i][j] + ab), sc[i][j]);
        __syncthreads();   // guard sA rebuild
    }

    // ---------- Phase D: softmax (warp-local, registers) + decay, write P ----------
    // Global max subtraction in reference is a scalar shift -> softmax invariant; skipped.
    #pragma unroll
    for (int i = 0; i < 4; i++) {
        float ev[7];
        float rs = 0.f;
        #pragma unroll
        for (int j = 0; j < 7; j++) {
            int k = lane + 32 * j;
            ev[j] = sValid[k] * __expf(sc[i][j]);
            rs += ev[j];
        }
        #pragma unroll
        for (int o = 16; o > 0; o >>= 1) rs += __shfl_xor_sync(0xffffffffu, rs, o);
        const float inv = __fdividef(1.f, rs);
        #pragma unroll
        for (int j = 0; j < 7; j++) {
            int k = lane + 32 * j;
            sP[(t0 + i) * 225 + k] = ev[j] * inv * sDecay[k];
        }
    }
    __syncthreads();

    // ---------- Phase E: context = P @ seq ----------
    {
        const int t  = tid >> 3;            // 0..63
        const int dg = (tid & 7) << 3;      // 0,8,...,56
        float o0 = 0.f, o1 = 0.f, o2 = 0.f, o3 = 0.f;
        float o4 = 0.f, o5 = 0.f, o6 = 0.f, o7 = 0.f;
        const float* pRow = sP + t * 225;
        #pragma unroll 4
        for (int k = 0; k < TK; k++) {
            const float  p  = pRow[k];
            const float4 s0 = *(const float4*)(sSeqRM + k * 64 + dg);
            const float4 s1 = *(const float4*)(sSeqRM + k * 64 + dg + 4);
            o0 = fmaf(p, s0.x, o0); o1 = fmaf(p, s0.y, o1);
            o2 = fmaf(p, s0.z, o2); o3 = fmaf(p, s0.w, o3);
            o4 = fmaf(p, s1.x, o4); o5 = fmaf(p, s1.y, o5);
            o6 = fmaf(p, s1.z, o6); o7 = fmaf(p, s1.w, o7);
        }
        float4* go = (float4*)(out + (size_t)b * TQ * DD + t * 64 + dg);
        go[0] = make_float4(o0, o1, o2, o3);
        go[1] = make_float4(o4, o5, o6, o7);
    }
}

extern "C" void kernel_launch(void* const* d_in, const int* in_sizes, int n_in,
                              void* d_out, int out_size)
{
    const float* seq    = (const float*)d_in[0];
    const float* dtn    = (const float*)d_in[1];
    const float* target = (const float*)d_in[2];
    const int*   vmask  = (const int*)  d_in[3];
    const float* fr     = (const float*)d_in[4];
    const float* fi     = (const float*)d_in[5];
    const float* Aw     = (const float*)d_in[6];
    const float* Ab     = (const float*)d_in[7];
    const float* Aout   = (const float*)d_in[8];
    float* out = (float*)d_out;

    const size_t shmem = SMEM_FLOATS * sizeof(float);
    cudaFuncSetAttribute(fta_kernel, cudaFuncAttributeMaxDynamicSharedMemorySize, (int)shmem);
    fta_kernel<<<BB, NTHREADS, shmem>>>(seq, dtn, target, vmask, fr, fi, Aw, Ab, Aout, out);
}

// round 3
// speedup vs baseline: 1.3742x; 1.3742x over previous
#include <cuda_runtime.h>
#include <cuda_bf16.h>
#include <cstdint>

#define BB 128
#define TQ 64
#define TK 200
#define TKP 224
#define DD 64
#define HH 10
#define NTHREADS 512

// seqT row stride in bytes (224 bf16 cols padded to 232 -> 464B; conflict-free for ldmatrix)
#define TSTRIDE 464

// ---- smem byte offsets ----
#define SEQT_HI_B  0                       // [64][464B] bf16 hi, transposed seq
#define SEQT_LO_B  29696                   // [64][464B] bf16 lo
#define SCORE_B    59392                   // float [64][226]
#define SEQF_B     117248                  // float [200][64]
#define TGT_B      168448                  // float [64][65]
#define AW_B       185088                  // float [10][64]
#define DEC_B      187648                  // float [224]
#define VAL_B      188544                  // float [224]
#define AB_B       189440                  // float [16]
#define AO_B       189504                  // float [16]
#define FR_B       189568                  // float [64]
#define FI_B       189824                  // float [64]
#define SMEM_TOTAL_B 190080

static __device__ __forceinline__ uint32_t smem_u32(const void* p) {
    uint32_t a;
    asm("{ .reg .u64 t; cvta.to.shared.u64 t, %1; cvt.u32.u64 %0, t; }" : "=r"(a) : "l"(p));
    return a;
}

static __device__ __forceinline__ void ldsm_x4t(uint32_t* r, uint32_t addr) {
    asm volatile("ldmatrix.sync.aligned.m8n8.x4.trans.shared.b16 {%0,%1,%2,%3}, [%4];"
                 : "=r"(r[0]), "=r"(r[1]), "=r"(r[2]), "=r"(r[3]) : "r"(addr));
}
static __device__ __forceinline__ void ldsm_x2t(uint32_t* r, uint32_t addr) {
    asm volatile("ldmatrix.sync.aligned.m8n8.x2.trans.shared.b16 {%0,%1}, [%2];"
                 : "=r"(r[0]), "=r"(r[1]) : "r"(addr));
}
static __device__ __forceinline__ void mma_bf16(float* c, const uint32_t* a, uint32_t b0, uint32_t b1) {
    asm volatile("mma.sync.aligned.m16n8k16.row.col.f32.bf16.bf16.f32 "
                 "{%0,%1,%2,%3}, {%4,%5,%6,%7}, {%8,%9}, {%0,%1,%2,%3};"
                 : "+f"(c[0]), "+f"(c[1]), "+f"(c[2]), "+f"(c[3])
                 : "r"(a[0]), "r"(a[1]), "r"(a[2]), "r"(a[3]), "r"(b0), "r"(b1));
}

// pack (x,y) to bf16x2 hi + bf16x2 lo (x in low 16 bits)
static __device__ __forceinline__ void splitpair(float x, float y, uint32_t& hi, uint32_t& lo) {
    __nv_bfloat162 h2 = __floats2bfloat162_rn(x, y);
    hi = *reinterpret_cast<uint32_t*>(&h2);
    float hx = __bfloat162float(__low2bfloat16(h2));
    float hy = __bfloat162float(__high2bfloat16(h2));
    __nv_bfloat162 l2 = __floats2bfloat162_rn(x - hx, y - hy);
    lo = *reinterpret_cast<uint32_t*>(&l2);
}

// odd Pade(7,6) tanh, |err| <~ 1e-4 with clamp; 1 MUFU (rcp) + FMAs
static __device__ __forceinline__ float tanh_pade(float x) {
    float t = x * x;
    float num = fmaf(t, fmaf(t, (t + 378.0f), 17325.0f), 135135.0f) * x;
    float den = fmaf(t, fmaf(t, fmaf(t, 28.0f, 3150.0f), 62370.0f), 135135.0f);
    float r = num * __frcp_rn(den);
    return fminf(fmaxf(r, -1.0f), 1.0f);
}

__global__ __launch_bounds__(NTHREADS, 1)
void fta_kernel(const float* __restrict__ seq,
                const float* __restrict__ dtn,
                const float* __restrict__ target,
                const int*   __restrict__ vmask,
                const float* __restrict__ fr,
                const float* __restrict__ fi,
                const float* __restrict__ Aw,
                const float* __restrict__ Ab,
                const float* __restrict__ Aout,
                float* __restrict__ out)
{
    extern __shared__ char smc[];
    const uint32_t sbase = smem_u32(smc);
    float* sScore = (float*)(smc + SCORE_B);
    float* sSeqF  = (float*)(smc + SEQF_B);
    float* sTgt   = (float*)(smc + TGT_B);
    float* sAw    = (float*)(smc + AW_B);
    float* sDec   = (float*)(smc + DEC_B);
    float* sVal   = (float*)(smc + VAL_B);
    float* sAb    = (float*)(smc + AB_B);
    float* sAo    = (float*)(smc + AO_B);
    float* sFr    = (float*)(smc + FR_B);
    float* sFi    = (float*)(smc + FI_B);

    const int b    = blockIdx.x;
    const int tid  = threadIdx.x;
    const int lane = tid & 31;
    const int warp = tid >> 5;

    // ---------------- Phase A: global -> smem ----------------
    {
        const float4* g4 = (const float4*)(seq + (size_t)b * TK * DD);
        float4* s4 = (float4*)sSeqF;
        for (int i = tid; i < TK * DD / 4; i += NTHREADS) s4[i] = g4[i];

        const float* gT = target + (size_t)b * TQ * DD;
        for (int i = tid; i < TQ * DD; i += NTHREADS) {
            int t = i >> 6, d = i & 63;
            sTgt[t * 65 + d] = gT[i];
        }
        for (int i = tid; i < HH * DD; i += NTHREADS) sAw[i] = Aw[i];
        if (tid < DD) { sFr[tid] = fr[tid]; sFi[tid] = fi[tid]; }
        if (tid < 16) {
            sAb[tid] = (tid < HH) ? Ab[tid]   : 0.f;
            sAo[tid] = (tid < HH) ? Aout[tid] : 0.f;
        }
    }
    __syncthreads();

    // ---------------- Phase B: transpose + bf16 hi/lo split; Fourier decay ----------------
    {
        const int d  = tid & 63;
        const int kg = tid >> 6;                 // 0..7, 28 tokens each
        char* rowHi = smc + SEQT_HI_B + d * TSTRIDE;
        char* rowLo = smc + SEQT_LO_B + d * TSTRIDE;
        for (int k = kg * 28; k < kg * 28 + 28; k += 2) {
            float x = (k     < TK) ? sSeqF[k * 64 + d]       : 0.f;
            float y = (k + 1 < TK) ? sSeqF[(k + 1) * 64 + d] : 0.f;
            uint32_t hi, lo; splitpair(x, y, hi, lo);
            *(uint32_t*)(rowHi + k * 2) = hi;
            *(uint32_t*)(rowLo + k * 2) = lo;
        }
    }
    if (tid < TKP) {
        float dec = 0.f, val = 0.f;
        if (tid < TK) {
            const int   m  = vmask[b * TK + tid];
            const float dt = dtn[b * TK + tid];
            const float th = (3.14159265358979323846f / 63.f) * dt;
            float acc = 0.f;
            #pragma unroll 8
            for (int j = 0; j < DD; j++) {
                float s, c;
                __sincosf(th * (float)j, &s, &c);
                acc = fmaf(c, sFr[j], acc);
                acc = fmaf(-s, sFi[j], acc);
            }
            float dcy = fminf(fmaxf(acc * (1.f / 128.f), 0.f), 1.f);
            if (m != 0) { dec = dcy; val = 1.f; }
        }
        sDec[tid] = dec;
        sVal[tid] = val;
    }
    __syncthreads();

    // ---------------- Phase C: per-warp 16x56 score tile, h-loop in registers ----------------
    {
        const int r  = warp >> 2, cq = warp & 3;
        const int t0 = r * 16, n0 = cq * 56;
        const int g  = lane >> 2;
        const int q2 = (lane & 3) * 2;

        // ldmatrix address components
        const uint32_t rowA  = (uint32_t)((lane & 7) + ((lane >> 3) & 1) * 8);
        const uint32_t colX4 = (uint32_t)((lane >> 4) * 8);
        const uint32_t bHiBase = sbase + SEQT_HI_B + rowA * TSTRIDE;
        const uint32_t bLoBase = sbase + SEQT_LO_B + rowA * TSTRIDE;

        const float* tgA = sTgt + (t0 + g) * 65;
        const float* tgB = tgA + 8 * 65;

        float sc[28];
        #pragma unroll
        for (int i = 0; i < 28; i++) sc[i] = 0.f;

        for (int h = 0; h < HH; h++) {
            float acc[28];
            #pragma unroll
            for (int i = 0; i < 28; i++) acc[i] = 0.f;
            const float* awh = sAw + h * 64;

            #pragma unroll
            for (int ks = 0; ks < 4; ks++) {
                // ---- A fragments in registers: a[r][k] = tgt[t][k] * aw[h][k], hi/lo split ----
                const int k0 = ks * 16 + q2;
                const float w0 = awh[k0],     w1 = awh[k0 + 1];
                const float w8 = awh[k0 + 8], w9 = awh[k0 + 9];
                uint32_t ah[4], al[4];
                splitpair(tgA[k0] * w0,     tgA[k0 + 1] * w1, ah[0], al[0]);
                splitpair(tgB[k0] * w0,     tgB[k0 + 1] * w1, ah[1], al[1]);
                splitpair(tgA[k0 + 8] * w8, tgA[k0 + 9] * w9, ah[2], al[2]);
                splitpair(tgB[k0 + 8] * w8, tgB[k0 + 9] * w9, ah[3], al[3]);

                // ---- B fragments via ldmatrix.trans ----
                const uint32_t rofs = (uint32_t)(ks * 16) * TSTRIDE;
                uint32_t bh[14], bl[14];
                #pragma unroll
                for (int j = 0; j < 3; j++) {
                    const uint32_t cofs = (uint32_t)(n0 + 16 * j) * 2 + colX4 * 2;
                    ldsm_x4t(bh + 4 * j, bHiBase + rofs + cofs);
                    ldsm_x4t(bl + 4 * j, bLoBase + rofs + cofs);
                }
                {
                    const uint32_t cofs = (uint32_t)(n0 + 48) * 2;
                    ldsm_x2t(bh + 12, bHiBase + rofs + cofs);
                    ldsm_x2t(bl + 12, bLoBase + rofs + cofs);
                }

                // ---- 3-pass emulated-fp32 MMA ----
                #pragma unroll
                for (int tI = 0; tI < 7; tI++) mma_bf16(acc + 4 * tI, ah, bh[2 * tI], bh[2 * tI + 1]);
                #pragma unroll
                for (int tI = 0; tI < 7; tI++) mma_bf16(acc + 4 * tI, ah, bl[2 * tI], bl[2 * tI + 1]);
                #pragma unroll
                for (int tI = 0; tI < 7; tI++) mma_bf16(acc + 4 * tI, al, bh[2 * tI], bh[2 * tI + 1]);
            }

            // ---- epilogue: score += ao * tanh(acc + ab) ----
            const float ao = sAo[h], abv = sAb[h];
            #pragma unroll
            for (int i = 0; i < 28; i++) sc[i] = fmaf(ao, tanh_pade(acc[i] + abv), sc[i]);
        }

        // ---- write score tile to smem ----
        float* s0 = sScore + (t0 + g) * 226 + n0 + q2;
        float* s1 = s0 + 8 * 226;
        #pragma unroll
        for (int tI = 0; tI < 7; tI++) {
            *(float2*)(s0 + 8 * tI) = make_float2(sc[4 * tI + 0], sc[4 * tI + 1]);
            *(float2*)(s1 + 8 * tI) = make_float2(sc[4 * tI + 2], sc[4 * tI + 3]);
        }
    }
    __syncthreads();

    // ---------------- Phase D: softmax + decay ----------------
    {
        const int t0 = warp * 4;
        #pragma unroll
        for (int i = 0; i < 4; i++) {
            float ev[7];
            float rs = 0.f;
            #pragma unroll
            for (int j = 0; j < 7; j++) {
                int k = lane + 32 * j;
                ev[j] = sVal[k] * __expf(sScore[(t0 + i) * 226 + k]);
                rs += ev[j];
            }
            #pragma unroll
            for (int o = 16; o > 0; o >>= 1) rs += __shfl_xor_sync(0xffffffffu, rs, o);
            const float inv = __fdividef(1.f, rs);
            #pragma unroll
            for (int j = 0; j < 7; j++) {
                int k = lane + 32 * j;
                sScore[(t0 + i) * 226 + k] = ev[j] * inv * sDec[k];
            }
        }
    }
    __syncthreads();

    // ---------------- Phase E: context = P @ seq ----------------
    {
        const int t  = tid >> 3;
        const int dg = (tid & 7) << 3;
        float o0 = 0.f, o1 = 0.f, o2 = 0.f, o3 = 0.f;
        float o4 = 0.f, o5 = 0.f, o6 = 0.f, o7 = 0.f;
        const float* pRow = sScore + t * 226;
        #pragma unroll 4
        for (int k = 0; k < TK; k++) {
            const float  p  = pRow[k];
            const float4 s0 = *(const float4*)(sSeqF + k * 64 + dg);
            const float4 s1 = *(const float4*)(sSeqF + k * 64 + dg + 4);
            o0 = fmaf(p, s0.x, o0); o1 = fmaf(p, s0.y, o1);
            o2 = fmaf(p, s0.z, o2); o3 = fmaf(p, s0.w, o3);
            o4 = fmaf(p, s1.x, o4); o5 = fmaf(p, s1.y, o5);
            o6 = fmaf(p, s1.z, o6); o7 = fmaf(p, s1.w, o7);
        }
        float4* go = (float4*)(out + (size_t)b * TQ * DD + t * 64 + dg);
        go[0] = make_float4(o0, o1, o2, o3);
        go[1] = make_float4(o4, o5, o6, o7);
    }
}

extern "C" void kernel_launch(void* const* d_in, const int* in_sizes, int n_in,
                              void* d_out, int out_size)
{
    const float* seq    = (const float*)d_in[0];
    const float* dtn    = (const float*)d_in[1];
    const float* target = (const float*)d_in[2];
    const int*   vmask  = (const int*)  d_in[3];
    const float* fr     = (const float*)d_in[4];
    const float* fi     = (const float*)d_in[5];
    const float* Aw     = (const float*)d_in[6];
    const float* Ab     = (const float*)d_in[7];
    const float* Aout   = (const float*)d_in[8];
    float* out = (float*)d_out;

    cudaFuncSetAttribute(fta_kernel, cudaFuncAttributeMaxDynamicSharedMemorySize, SMEM_TOTAL_B);
    fta_kernel<<<BB, NTHREADS, SMEM_TOTAL_B>>>(seq, dtn, target, vmask, fr, fi, Aw, Ab, Aout, out);
}

// round 5
// speedup vs baseline: 3.1736x; 2.3095x over previous
#include <cuda_runtime.h>
#include <cuda_fp16.h>
#include <cstdint>

#define BB 128
#define TQ 64
#define TK 200
#define TKP 224
#define DD 64
#define HH 10
#define NTHREADS 512

#define TSTRIDE 464            // seqT row stride bytes (fp16, 224 cols + pad)
#define ASTRIDE 144            // A / SEQK row stride bytes (72 fp16)
#define PSTRIDE 432            // P row stride bytes (216 fp16)

// ---- smem byte offsets ----
#define SEQT_B   0             // fp16 seq transposed [64d][464B]      29,696
#define P_B      0             // alias: fp16 P [64t][432B]            27,648 (phase D/E)
#define ABUF0_B  29696         // fp16 A [64t][144B]                    9,216
#define ABUF1_B  38912         //                                       9,216
#define SCORE_B  48128         // float [64][226]                      57,824
#define SEQK_B   105952        // fp16 seq k-major [208][144B]         29,952
#define TGT_B    135904        // float [64][65]                       16,640
#define AW_B     152544        // float [10][64] (x256)                 2,560
#define DEC_B    155104        // float [224]
#define VAL_B    156000        // float [224]
#define AB_B     156896        // float [16]
#define AO_B     156960        // float [16]
#define FR_B     157024        // float [64]
#define FI_B     157280        // float [64]
#define SMEM_TOTAL_B 157536

static __device__ __forceinline__ uint32_t smem_u32(const void* p) {
    uint32_t a;
    asm("{ .reg .u64 t; cvta.to.shared.u64 t, %1; cvt.u32.u64 %0, t; }" : "=r"(a) : "l"(p));
    return a;
}
static __device__ __forceinline__ void ldsm_x4(uint32_t* r, uint32_t addr) {
    asm volatile("ldmatrix.sync.aligned.m8n8.x4.shared.b16 {%0,%1,%2,%3}, [%4];"
                 : "=r"(r[0]), "=r"(r[1]), "=r"(r[2]), "=r"(r[3]) : "r"(addr));
}
static __device__ __forceinline__ void ldsm_x4t(uint32_t* r, uint32_t addr) {
    asm volatile("ldmatrix.sync.aligned.m8n8.x4.trans.shared.b16 {%0,%1,%2,%3}, [%4];"
                 : "=r"(r[0]), "=r"(r[1]), "=r"(r[2]), "=r"(r[3]) : "r"(addr));
}
static __device__ __forceinline__ void ldsm_x2t(uint32_t* r, uint32_t addr) {
    asm volatile("ldmatrix.sync.aligned.m8n8.x2.trans.shared.b16 {%0,%1}, [%2];"
                 : "=r"(r[0]), "=r"(r[1]) : "r"(addr));
}
static __device__ __forceinline__ void mma_f16(float* c, const uint32_t* a, uint32_t b0, uint32_t b1) {
    asm volatile("mma.sync.aligned.m16n8k16.row.col.f32.f16.f16.f32 "
                 "{%0,%1,%2,%3}, {%4,%5,%6,%7}, {%8,%9}, {%0,%1,%2,%3};"
                 : "+f"(c[0]), "+f"(c[1]), "+f"(c[2]), "+f"(c[3])
                 : "r"(a[0]), "r"(a[1]), "r"(a[2]), "r"(a[3]), "r"(b0), "r"(b1));
}
static __device__ __forceinline__ float ex2f(float x) {
    float y; asm("ex2.approx.f32 %0, %1;" : "=f"(y) : "f"(x)); return y;
}
static __device__ __forceinline__ float rcpf(float x) {
    float y; asm("rcp.approx.f32 %0, %1;" : "=f"(y) : "f"(x)); return y;
}

__global__ __launch_bounds__(NTHREADS, 1)
void fta_kernel(const float* __restrict__ seq,
                const float* __restrict__ dtn,
                const float* __restrict__ target,
                const int*   __restrict__ vmask,
                const float* __restrict__ fr,
                const float* __restrict__ fi,
                const float* __restrict__ Aw,
                const float* __restrict__ Ab,
                const float* __restrict__ Aout,
                float* __restrict__ out)
{
    extern __shared__ char smc[];
    const uint32_t sbase = smem_u32(smc);
    float* sScore = (float*)(smc + SCORE_B);
    float* sTgt   = (float*)(smc + TGT_B);
    float* sAw    = (float*)(smc + AW_B);
    float* sDec   = (float*)(smc + DEC_B);
    float* sVal   = (float*)(smc + VAL_B);
    float* sAb    = (float*)(smc + AB_B);
    float* sAo    = (float*)(smc + AO_B);
    float* sFr    = (float*)(smc + FR_B);
    float* sFi    = (float*)(smc + FI_B);

    const int b    = blockIdx.x;
    const int tid  = threadIdx.x;
    const int lane = tid & 31;
    const int warp = tid >> 5;

    // ---------------- Phase A: gmem -> smem (fp16 seqT, fp16 seqK, fp32 tgt) ----------------
    {
        const float4* g4 = (const float4*)(seq + (size_t)b * TK * DD);
        for (int i = tid; i < TKP * 16; i += NTHREADS) {
            int k = i >> 4, d4 = i & 15;
            float4 v = make_float4(0.f, 0.f, 0.f, 0.f);
            if (k < TK) v = g4[k * 16 + d4];
            __half2 h01 = __floats2half2_rn(v.x, v.y);
            __half2 h23 = __floats2half2_rn(v.z, v.w);
            if (k < 208) {
                *(__half2*)(smc + SEQK_B + k * ASTRIDE + d4 * 8)     = h01;
                *(__half2*)(smc + SEQK_B + k * ASTRIDE + d4 * 8 + 4) = h23;
            }
            // transposed scatter
            int d = d4 * 4;
            *(__half*)(smc + SEQT_B + (d + 0) * TSTRIDE + k * 2) = __low2half(h01);
            *(__half*)(smc + SEQT_B + (d + 1) * TSTRIDE + k * 2) = __high2half(h01);
            *(__half*)(smc + SEQT_B + (d + 2) * TSTRIDE + k * 2) = __low2half(h23);
            *(__half*)(smc + SEQT_B + (d + 3) * TSTRIDE + k * 2) = __high2half(h23);
        }
        const float* gT = target + (size_t)b * TQ * DD;
        for (int i = tid; i < TQ * DD; i += NTHREADS) {
            int t = i >> 6, d = i & 63;
            sTgt[t * 65 + d] = gT[i];
        }
        for (int i = tid; i < HH * DD; i += NTHREADS) sAw[i] = Aw[i] * 256.0f;
        if (tid < DD) { sFr[tid] = fr[tid]; sFi[tid] = fi[tid]; }
        if (tid < 16) {
            sAb[tid] = (tid < HH) ? Ab[tid]   : 0.f;
            sAo[tid] = (tid < HH) ? Aout[tid] : 0.f;
        }
    }
    __syncthreads();

    // ---------------- Phase B: Fourier decay + build A[0] ----------------
    if (tid < TKP) {
        float dec = 0.f, val = 0.f;
        if (tid < TK) {
            const int   m  = vmask[b * TK + tid];
            const float dt = dtn[b * TK + tid];
            const float th = (3.14159265358979323846f / 63.f) * dt;
            float acc = 0.f;
            #pragma unroll 8
            for (int j = 0; j < DD; j++) {
                float s, c;
                __sincosf(th * (float)j, &s, &c);
                acc = fmaf(c, sFr[j], acc);
                acc = fmaf(-s, sFi[j], acc);
            }
            float dcy = fminf(fmaxf(acc * (1.f / 128.f), 0.f), 1.f);
            if (m != 0) { dec = dcy; val = 1.f; }
        }
        sDec[tid] = dec;
        sVal[tid] = val;
    }
    #pragma unroll
    for (int n = 0; n < 4; n++) {
        int idx = tid + n * NTHREADS;
        int t = idx >> 5, dp = (idx & 31) * 2;
        float a0 = sTgt[t * 65 + dp]     * sAw[dp];
        float a1 = sTgt[t * 65 + dp + 1] * sAw[dp + 1];
        *(__half2*)(smc + ABUF0_B + t * ASTRIDE + dp * 2) = __floats2half2_rn(a0, a1);
    }
    __syncthreads();

    // ---------------- Phase C: score GEMM, h-loop with double-buffered A ----------------
    {
        const int r  = warp >> 2, cq = warp & 3;
        const int t0 = r * 16, n0 = cq * 56;
        const int g  = lane >> 2;
        const int q2 = (lane & 3) * 2;
        const uint32_t rowSel = (uint32_t)((lane & 7) + ((lane >> 3) & 1) * 8);
        const uint32_t colX4  = (uint32_t)((lane >> 4) * 8);
        const uint32_t aAddr0 = sbase + (uint32_t)((t0 + rowSel) * ASTRIDE) + colX4 * 2;
        const uint32_t bBase  = sbase + SEQT_B + rowSel * TSTRIDE;

        float sc[28];
        #pragma unroll
        for (int i = 0; i < 28; i++) sc[i] = 0.f;

        for (int h = 0; h < HH; h++) {
            const uint32_t abufO = (h & 1) ? ABUF1_B : ABUF0_B;
            uint32_t af[4][4];
            #pragma unroll
            for (int ks = 0; ks < 4; ks++) ldsm_x4(af[ks], aAddr0 + abufO + ks * 32);

            float acc[28];
            #pragma unroll
            for (int i = 0; i < 28; i++) acc[i] = 0.f;

            #pragma unroll
            for (int ks = 0; ks < 4; ks++) {
                const uint32_t base = bBase + (uint32_t)(ks * 16) * TSTRIDE;
                uint32_t bb[14];
                ldsm_x4t(bb + 0, base + (uint32_t)(n0)      * 2 + colX4 * 2);
                ldsm_x4t(bb + 4, base + (uint32_t)(n0 + 16) * 2 + colX4 * 2);
                ldsm_x4t(bb + 8, base + (uint32_t)(n0 + 32) * 2 + colX4 * 2);
                ldsm_x2t(bb + 12, base + (uint32_t)(n0 + 48) * 2);
                #pragma unroll
                for (int tI = 0; tI < 7; tI++) mma_f16(acc + 4 * tI, af[ks], bb[2 * tI], bb[2 * tI + 1]);
            }

            // build next A (independent of MMAs -> overlaps)
            if (h + 1 < HH) {
                const int hn = h + 1;
                const uint32_t abufN = (hn & 1) ? ABUF1_B : ABUF0_B;
                #pragma unroll
                for (int n = 0; n < 4; n++) {
                    int idx = tid + n * NTHREADS;
                    int t = idx >> 5, dp = (idx & 31) * 2;
                    float a0 = sTgt[t * 65 + dp]     * sAw[hn * 64 + dp];
                    float a1 = sTgt[t * 65 + dp + 1] * sAw[hn * 64 + dp + 1];
                    *(__half2*)(smc + abufN + t * ASTRIDE + dp * 2) = __floats2half2_rn(a0, a1);
                }
            }

            // epilogue: sc += ao * tanh(acc/256 + ab) via tanh = 1 - 2/(e^2x + 1)
            const float ao   = sAo[h];
            const float c2   = sAb[h] * 2.8853900817779268f;   // 2*log2(e)*ab
            const float m2ao = -2.0f * ao;
            #pragma unroll
            for (int i = 0; i < 28; i++) {
                float f = fmaf(acc[i], 0.0112710550069450f, c2); // acc * 2*log2e/256
                float e = ex2f(f);
                float rc = rcpf(e + 1.0f);
                sc[i] = fmaf(m2ao, rc, sc[i] + ao);
            }
            __syncthreads();
        }

        // write score tile
        float* s0 = sScore + (t0 + g) * 226 + n0 + q2;
        float* s1 = s0 + 8 * 226;
        #pragma unroll
        for (int tI = 0; tI < 7; tI++) {
            *(float2*)(s0 + 8 * tI) = make_float2(sc[4 * tI + 0], sc[4 * tI + 1]);
            *(float2*)(s1 + 8 * tI) = make_float2(sc[4 * tI + 2], sc[4 * tI + 3]);
        }
    }
    __syncthreads();

    // ---------------- Phase D: softmax + decay -> P (fp16) ----------------
    {
        const int t0 = warp * 4;
        #pragma unroll
        for (int i = 0; i < 4; i++) {
            float ev[7];
            float rs = 0.f;
            #pragma unroll
            for (int j = 0; j < 7; j++) {
                int k = lane + 32 * j;
                ev[j] = sVal[k] * __expf(sScore[(t0 + i) * 226 + k]);
                rs += ev[j];
            }
            #pragma unroll
            for (int o = 16; o > 0; o >>= 1) rs += __shfl_xor_sync(0xffffffffu, rs, o);
            const float inv = __fdividef(1.f, rs);
            #pragma unroll
            for (int j = 0; j < 7; j++) {
                int k = lane + 32 * j;
                if (k < 216)
                    *(__half*)(smc + P_B + (t0 + i) * PSTRIDE + k * 2) =
                        __float2half_rn(ev[j] * inv * sDec[k]);
            }
        }
    }
    __syncthreads();

    // ---------------- Phase E: context = P @ seq via MMA ----------------
    {
        const int t0e = (warp >> 2) * 16;
        const int d0  = (warp & 3) * 16;
        const uint32_t rowSel = (uint32_t)((lane & 7) + ((lane >> 3) & 1) * 8);
        const uint32_t pBase = sbase + P_B + (uint32_t)((t0e + rowSel) * PSTRIDE) + (uint32_t)((lane >> 4) * 16);
        const uint32_t kBase = sbase + SEQK_B + rowSel * ASTRIDE + (uint32_t)((d0 + (lane >> 4) * 8) * 2);

        float accA[4] = {0.f, 0.f, 0.f, 0.f};
        float accB[4] = {0.f, 0.f, 0.f, 0.f};
        #pragma unroll
        for (int kc = 0; kc < 13; kc++) {
            uint32_t a[4], bb[4];
            ldsm_x4(a, pBase + (uint32_t)(kc * 32));
            ldsm_x4t(bb, kBase + (uint32_t)(kc * 16) * ASTRIDE);
            mma_f16(accA, a, bb[0], bb[1]);
            mma_f16(accB, a, bb[2], bb[3]);
        }
        float* gout = out + (size_t)b * TQ * DD;
        const int rr = lane >> 2, cc = (lane & 3) * 2;
        *(float2*)(gout + (t0e + rr) * 64 + d0 + cc)         = make_float2(accA[0], accA[1]);
        *(float2*)(gout + (t0e + rr + 8) * 64 + d0 + cc)     = make_float2(accA[2], accA[3]);
        *(float2*)(gout + (t0e + rr) * 64 + d0 + 8 + cc)     = make_float2(accB[0], accB[1]);
        *(float2*)(gout + (t0e + rr + 8) * 64 + d0 + 8 + cc) = make_float2(accB[2], accB[3]);
    }
}

extern "C" void kernel_launch(void* const* d_in, const int* in_sizes, int n_in,
                              void* d_out, int out_size)
{
    const float* seq    = (const float*)d_in[0];
    const float* dtn    = (const float*)d_in[1];
    const float* target = (const float*)d_in[2];
    const int*   vmask  = (const int*)  d_in[3];
    const float* fr     = (const float*)d_in[4];
    const float* fi     = (const float*)d_in[5];
    const float* Aw     = (const float*)d_in[6];
    const float* Ab     = (const float*)d_in[7];
    const float* Aout   = (const float*)d_in[8];
    float* out = (float*)d_out;

    cudaFuncSetAttribute(fta_kernel, cudaFuncAttributeMaxDynamicSharedMemorySize, SMEM_TOTAL_B);
    fta_kernel<<<BB, NTHREADS, SMEM_TOTAL_B>>>(seq, dtn, target, vmask, fr, fi, Aw, Ab, Aout, out);
}

// round 6
// speedup vs baseline: 4.8814x; 1.5381x over previous
#include <cuda_runtime.h>
#include <cuda_fp16.h>
#include <cstdint>

#define BB 128
#define TQ 64
#define TK 200
#define TKP 224
#define DD 64
#define HH 10
#define NTHREADS 512

#define TSTRIDE 464            // seqT row stride bytes (fp16, 224 cols + pad)
#define ASTRIDE 144            // A / SEQK row stride bytes (72 fp16)
#define PSTRIDE 432            // P row stride bytes (216 fp16)

// ---- smem byte offsets ----
#define SEQT_B   0             // fp16 seq transposed [64d][464B]      29,696
#define P_B      0             // alias: fp16 P [64t][432B] (phase D/E)
#define SEQK_B   29696         // fp16 seq k-major [208][144B]         29,952
#define ABUF_B   59648         // fp16 A[10][64t][144B]                92,160
#define TGT_B    151808        // float [64][65]                       16,640
#define AW_B     168448        // float [10][64] (x256)                 2,560
#define DEC_B    171008        // float [224]                             896
#define VAL_B    171904        // float [224]                             896
#define AB_B     172800        // float [16]
#define AO_B     172864        // float [16]
#define FR_B     172928        // float [64]
#define FI_B     173184        // float [64]
#define PART_B   173440        // float [64][4] row partial sums        1,024
#define SMEM_TOTAL_B 174464

static __device__ __forceinline__ uint32_t smem_u32(const void* p) {
    uint32_t a;
    asm("{ .reg .u64 t; cvta.to.shared.u64 t, %1; cvt.u32.u64 %0, t; }" : "=r"(a) : "l"(p));
    return a;
}
static __device__ __forceinline__ void ldsm_x4(uint32_t* r, uint32_t addr) {
    asm volatile("ldmatrix.sync.aligned.m8n8.x4.shared.b16 {%0,%1,%2,%3}, [%4];"
                 : "=r"(r[0]), "=r"(r[1]), "=r"(r[2]), "=r"(r[3]) : "r"(addr));
}
static __device__ __forceinline__ void ldsm_x4t(uint32_t* r, uint32_t addr) {
    asm volatile("ldmatrix.sync.aligned.m8n8.x4.trans.shared.b16 {%0,%1,%2,%3}, [%4];"
                 : "=r"(r[0]), "=r"(r[1]), "=r"(r[2]), "=r"(r[3]) : "r"(addr));
}
static __device__ __forceinline__ void ldsm_x2t(uint32_t* r, uint32_t addr) {
    asm volatile("ldmatrix.sync.aligned.m8n8.x2.trans.shared.b16 {%0,%1}, [%2];"
                 : "=r"(r[0]), "=r"(r[1]) : "r"(addr));
}
static __device__ __forceinline__ void mma_f16(float* c, const uint32_t* a, uint32_t b0, uint32_t b1) {
    asm volatile("mma.sync.aligned.m16n8k16.row.col.f32.f16.f16.f32 "
                 "{%0,%1,%2,%3}, {%4,%5,%6,%7}, {%8,%9}, {%0,%1,%2,%3};"
                 : "+f"(c[0]), "+f"(c[1]), "+f"(c[2]), "+f"(c[3])
                 : "r"(a[0]), "r"(a[1]), "r"(a[2]), "r"(a[3]), "r"(b0), "r"(b1));
}
static __device__ __forceinline__ float htanh(float x) {
    float y; asm("tanh.approx.f32 %0, %1;" : "=f"(y) : "f"(x)); return y;
}

__global__ __launch_bounds__(NTHREADS, 1)
void fta_kernel(const float* __restrict__ seq,
                const float* __restrict__ dtn,
                const float* __restrict__ target,
                const int*   __restrict__ vmask,
                const float* __restrict__ fr,
                const float* __restrict__ fi,
                const float* __restrict__ Aw,
                const float* __restrict__ Ab,
                const float* __restrict__ Aout,
                float* __restrict__ out)
{
    extern __shared__ char smc[];
    const uint32_t sbase = smem_u32(smc);
    float* sTgt  = (float*)(smc + TGT_B);
    float* sAw   = (float*)(smc + AW_B);
    float* sDec  = (float*)(smc + DEC_B);
    float* sVal  = (float*)(smc + VAL_B);
    float* sAb   = (float*)(smc + AB_B);
    float* sAo   = (float*)(smc + AO_B);
    float* sFr   = (float*)(smc + FR_B);
    float* sFi   = (float*)(smc + FI_B);
    float* sPart = (float*)(smc + PART_B);

    const int b    = blockIdx.x;
    const int tid  = threadIdx.x;
    const int lane = tid & 31;
    const int warp = tid >> 5;

    // ---------------- Phase A: gmem -> smem (fp16 seqT, fp16 seqK, fp32 tgt) ----------------
    {
        const float4* g4 = (const float4*)(seq + (size_t)b * TK * DD);
        for (int i = tid; i < TKP * 16; i += NTHREADS) {
            int k = i >> 4, d4 = i & 15;
            float4 v = make_float4(0.f, 0.f, 0.f, 0.f);
            if (k < TK) v = g4[k * 16 + d4];
            __half2 h01 = __floats2half2_rn(v.x, v.y);
            __half2 h23 = __floats2half2_rn(v.z, v.w);
            if (k < 208) {
                *(__half2*)(smc + SEQK_B + k * ASTRIDE + d4 * 8)     = h01;
                *(__half2*)(smc + SEQK_B + k * ASTRIDE + d4 * 8 + 4) = h23;
            }
            int d = d4 * 4;
            *(__half*)(smc + SEQT_B + (d + 0) * TSTRIDE + k * 2) = __low2half(h01);
            *(__half*)(smc + SEQT_B + (d + 1) * TSTRIDE + k * 2) = __high2half(h01);
            *(__half*)(smc + SEQT_B + (d + 2) * TSTRIDE + k * 2) = __low2half(h23);
            *(__half*)(smc + SEQT_B + (d + 3) * TSTRIDE + k * 2) = __high2half(h23);
        }
        const float* gT = target + (size_t)b * TQ * DD;
        for (int i = tid; i < TQ * DD; i += NTHREADS) {
            int t = i >> 6, d = i & 63;
            sTgt[t * 65 + d] = gT[i];
        }
        for (int i = tid; i < HH * DD; i += NTHREADS) sAw[i] = Aw[i] * 256.0f;
        if (tid < DD) { sFr[tid] = fr[tid]; sFi[tid] = fi[tid]; }
        if (tid < 16) {
            sAb[tid] = (tid < HH) ? Ab[tid]   : 0.f;
            sAo[tid] = (tid < HH) ? Aout[tid] : 0.f;
        }
    }
    __syncthreads();

    // ---------------- Phase B: Fourier decay + build ALL 10 A tiles ----------------
    if (tid < TKP) {
        float dec = 0.f, val = 0.f;
        if (tid < TK) {
            const int   m  = vmask[b * TK + tid];
            const float dt = dtn[b * TK + tid];
            const float th = (3.14159265358979323846f / 63.f) * dt;
            float acc = 0.f;
            #pragma unroll 8
            for (int j = 0; j < DD; j++) {
                float s, c;
                __sincosf(th * (float)j, &s, &c);
                acc = fmaf(c, sFr[j], acc);
                acc = fmaf(-s, sFi[j], acc);
            }
            float dcy = fminf(fmaxf(acc * (1.f / 128.f), 0.f), 1.f);
            if (m != 0) { dec = dcy; val = 1.f; }
        }
        sDec[tid] = dec;
        sVal[tid] = val;
    }
    #pragma unroll
    for (int n = 0; n < HH * 2048 / NTHREADS; n++) {       // 40 iters
        int i = tid + n * NTHREADS;
        int h = i >> 11, rem = i & 2047;
        int t = rem >> 5, dp = (rem & 31) << 1;
        float a0 = sTgt[t * 65 + dp]     * sAw[h * 64 + dp];
        float a1 = sTgt[t * 65 + dp + 1] * sAw[h * 64 + dp + 1];
        *(__half2*)(smc + ABUF_B + h * 9216 + t * ASTRIDE + dp * 2) = __floats2half2_rn(a0, a1);
    }
    __syncthreads();

    // ---------------- Phase C: score GEMM, sync-free h-loop ----------------
    const int r  = warp >> 2, cq = warp & 3;
    const int t0 = r * 16, n0 = cq * 56;
    const int g  = lane >> 2;
    const int q2 = (lane & 3) * 2;

    float sc[28];
    {
        const uint32_t rowSel = (uint32_t)((lane & 7) + ((lane >> 3) & 1) * 8);
        const uint32_t colX4  = (uint32_t)((lane >> 4) * 8);
        const uint32_t aBase  = sbase + ABUF_B + (uint32_t)((t0 + rowSel) * ASTRIDE) + colX4 * 2;
        const uint32_t bBase  = sbase + SEQT_B + rowSel * TSTRIDE;

        #pragma unroll
        for (int i = 0; i < 28; i++) sc[i] = 0.f;

        for (int h = 0; h < HH; h++) {
            const uint32_t aAddr = aBase + (uint32_t)(h * 9216);
            uint32_t af[4][4];
            #pragma unroll
            for (int ks = 0; ks < 4; ks++) ldsm_x4(af[ks], aAddr + ks * 32);

            float acc[28];
            #pragma unroll
            for (int i = 0; i < 28; i++) acc[i] = 0.f;

            #pragma unroll
            for (int ks = 0; ks < 4; ks++) {
                const uint32_t base = bBase + (uint32_t)(ks * 16) * TSTRIDE;
                uint32_t bb[14];
                ldsm_x4t(bb + 0, base + (uint32_t)(n0)      * 2 + colX4 * 2);
                ldsm_x4t(bb + 4, base + (uint32_t)(n0 + 16) * 2 + colX4 * 2);
                ldsm_x4t(bb + 8, base + (uint32_t)(n0 + 32) * 2 + colX4 * 2);
                ldsm_x2t(bb + 12, base + (uint32_t)(n0 + 48) * 2);
                #pragma unroll
                for (int tI = 0; tI < 7; tI++) mma_f16(acc + 4 * tI, af[ks], bb[2 * tI], bb[2 * tI + 1]);
            }

            // sc += ao * tanh(acc/256 + ab)  (hardware tanh, 1 MUFU)
            const float ao = sAo[h], abv = sAb[h];
            #pragma unroll
            for (int i = 0; i < 28; i++) {
                float x = fmaf(acc[i], 0.00390625f, abv);
                sc[i] = fmaf(ao, htanh(x), sc[i]);
            }
        }
    }

    // ---------------- Phase D: softmax + decay from registers -> fp16 P ----------------
    {
        float ev[28];
        float se = 0.f, so = 0.f;
        #pragma unroll
        for (int j = 0; j < 7; j++) {
            int c = n0 + q2 + 8 * j;
            float2 v = *(float2*)&sVal[c];
            float e0 = v.x * __expf(sc[4 * j + 0]);
            float e1 = v.y * __expf(sc[4 * j + 1]);
            float e2 = v.x * __expf(sc[4 * j + 2]);
            float e3 = v.y * __expf(sc[4 * j + 3]);
            ev[4 * j + 0] = e0; ev[4 * j + 1] = e1;
            ev[4 * j + 2] = e2; ev[4 * j + 3] = e3;
            se += e0 + e1;
            so += e2 + e3;
        }
        se += __shfl_xor_sync(0xffffffffu, se, 1);
        se += __shfl_xor_sync(0xffffffffu, se, 2);
        so += __shfl_xor_sync(0xffffffffu, so, 1);
        so += __shfl_xor_sync(0xffffffffu, so, 2);
        if ((lane & 3) == 0) {
            sPart[(t0 + g) * 4 + cq]     = se;
            sPart[(t0 + g + 8) * 4 + cq] = so;
        }
        __syncthreads();   // all warps done with phase C + partials visible

        float4 pe = *(float4*)&sPart[(t0 + g) * 4];
        float4 po = *(float4*)&sPart[(t0 + g + 8) * 4];
        const float invE = __fdividef(1.f, pe.x + pe.y + pe.z + pe.w);
        const float invO = __fdividef(1.f, po.x + po.y + po.z + po.w);

        char* rowE = smc + P_B + (t0 + g) * PSTRIDE;
        char* rowO = smc + P_B + (t0 + g + 8) * PSTRIDE;
        #pragma unroll
        for (int j = 0; j < 7; j++) {
            int c = n0 + q2 + 8 * j;
            if (c < 216) {
                float2 d = *(float2*)&sDec[c];
                *(__half2*)(rowE + c * 2) =
                    __floats2half2_rn(ev[4 * j + 0] * invE * d.x, ev[4 * j + 1] * invE * d.y);
                *(__half2*)(rowO + c * 2) =
                    __floats2half2_rn(ev[4 * j + 2] * invO * d.x, ev[4 * j + 3] * invO * d.y);
            }
        }
    }
    __syncthreads();

    // ---------------- Phase E: context = P @ seq via MMA ----------------
    {
        const int t0e = (warp >> 2) * 16;
        const int d0  = (warp & 3) * 16;
        const uint32_t rowSel = (uint32_t)((lane & 7) + ((lane >> 3) & 1) * 8);
        const uint32_t pBase = sbase + P_B + (uint32_t)((t0e + rowSel) * PSTRIDE) + (uint32_t)((lane >> 4) * 16);
        const uint32_t kBase = sbase + SEQK_B + rowSel * ASTRIDE + (uint32_t)((d0 + (lane >> 4) * 8) * 2);

        float accA[4] = {0.f, 0.f, 0.f, 0.f};
        float accB[4] = {0.f, 0.f, 0.f, 0.f};
        #pragma unroll
        for (int kc = 0; kc < 13; kc++) {
            uint32_t a[4], bb[4];
            ldsm_x4(a, pBase + (uint32_t)(kc * 32));
            ldsm_x4t(bb, kBase + (uint32_t)(kc * 16) * ASTRIDE);
            mma_f16(accA, a, bb[0], bb[1]);
            mma_f16(accB, a, bb[2], bb[3]);
        }
        float* gout = out + (size_t)b * TQ * DD;
        const int rr = lane >> 2, cc = (lane & 3) * 2;
        *(float2*)(gout + (t0e + rr) * 64 + d0 + cc)         = make_float2(accA[0], accA[1]);
        *(float2*)(gout + (t0e + rr + 8) * 64 + d0 + cc)     = make_float2(accA[2], accA[3]);
        *(float2*)(gout + (t0e + rr) * 64 + d0 + 8 + cc)     = make_float2(accB[0], accB[1]);
        *(float2*)(gout + (t0e + rr + 8) * 64 + d0 + 8 + cc) = make_float2(accB[2], accB[3]);
    }
}

extern "C" void kernel_launch(void* const* d_in, const int* in_sizes, int n_in,
                              void* d_out, int out_size)
{
    const float* seq    = (const float*)d_in[0];
    const float* dtn    = (const float*)d_in[1];
    const float* target = (const float*)d_in[2];
    const int*   vmask  = (const int*)  d_in[3];
    const float* fr     = (const float*)d_in[4];
    const float* fi     = (const float*)d_in[5];
    const float* Aw     = (const float*)d_in[6];
    const float* Ab     = (const float*)d_in[7];
    const float* Aout   = (const float*)d_in[8];
    float* out = (float*)d_out;

    cudaFuncSetAttribute(fta_kernel, cudaFuncAttributeMaxDynamicSharedMemorySize, SMEM_TOTAL_B);
    fta_kernel<<<BB, NTHREADS, SMEM_TOTAL_B>>>(seq, dtn, target, vmask, fr, fi, Aw, Ab, Aout, out);
}